// round 10
// baseline (speedup 1.0000x reference)
#include <cuda_runtime.h>
#include <cuda_bf16.h>
#include <cuda_fp16.h>
#include <math.h>
#include <cstdint>

#define HD       128
#define MAXN     50000
#define MAXN_PAD 50048            // 782 * 64
#define MAXE     1600000
#define TILES    (MAXN_PAD / 16)  // 3128 (16-row warp tiles)
#define KSTEPS   8

// ---------------------------------------------------------------------------
// Device scratch (allocation-free per harness rules)
// ---------------------------------------------------------------------------
__device__ float g_Q[MAXN_PAD * HD];
// Interleaved K/V, fp16: g_KV[node*32 + l] = {K2(4l),K2(4l+2),V2(4l),V2(4l+2)}
__device__ uint4 g_KV[MAXN_PAD * 32];

// Fragment-major A (bf16 hi/lo): [tile][kstep][lane] -> uint4 (4 b32 = 8 bf16)
__device__ uint4 g_Afrag_hi[TILES * KSTEPS * 32];
__device__ uint4 g_Afrag_lo[TILES * KSTEPS * 32];
// Fragment-major B: [mat][kstep][ntile][lane] -> uint4 {b0hi,b1hi,b0lo,b1lo}
__device__ uint4 g_Bfrag[3 * KSTEPS * 16 * 32];

// CSR sort scratch
__device__ int g_cnt[MAXN];
__device__ int g_off[MAXN + 1];
__device__ int g_pos[MAXN];
__device__ int g_esrc[MAXE];

// ---------------------------------------------------------------------------
// Helpers
// ---------------------------------------------------------------------------
__device__ __forceinline__ uint32_t smem_u32(const void* p) {
    uint32_t a;
    asm("{ .reg .u64 t; cvta.to.shared.u64 t, %1; cvt.u32.u64 %0, t; }"
        : "=r"(a) : "l"(p));
    return a;
}

__device__ __forceinline__ void split2(float x, float y, uint32_t& hi, uint32_t& lo) {
    __nv_bfloat16 hx = __float2bfloat16(x);
    __nv_bfloat16 hy = __float2bfloat16(y);
    __nv_bfloat16 lx = __float2bfloat16(x - __bfloat162float(hx));
    __nv_bfloat16 ly = __float2bfloat16(y - __bfloat162float(hy));
    __nv_bfloat162 H(hx, hy), L(lx, ly);
    hi = *(uint32_t*)&H;
    lo = *(uint32_t*)&L;
}

#define MMA16816(c, a0, a1, a2, a3, b0, b1)                                  \
    asm volatile(                                                            \
        "mma.sync.aligned.m16n8k16.row.col.f32.bf16.bf16.f32 "              \
        "{%0,%1,%2,%3}, {%4,%5,%6,%7}, {%8,%9}, {%0,%1,%2,%3};"             \
        : "+f"((c)[0]), "+f"((c)[1]), "+f"((c)[2]), "+f"((c)[3])             \
        : "r"(a0), "r"(a1), "r"(a2), "r"(a3), "r"(b0), "r"(b1))

// ---------------------------------------------------------------------------
// prep_A: h (fp32) -> bf16 hi/lo fragments. One thread per (tile, kstep, lane).
// ---------------------------------------------------------------------------
__global__ void prep_A(const float* __restrict__ h, int n) {
    int idx = blockIdx.x * blockDim.x + threadIdx.x;
    int lane = idx & 31;
    int s    = (idx >> 5) & 7;
    int t    = idx >> 8;
    if (t >= TILES) return;

    int r1 = t * 16 + (lane >> 2);
    int r2 = r1 + 8;
    int c0 = s * 16 + (lane & 3) * 2;

    float2 x00 = make_float2(0.f, 0.f), x10 = x00, x01 = x00, x11 = x00;
    if (r1 < n) {
        x00 = *(const float2*)&h[(size_t)r1 * HD + c0];
        x01 = *(const float2*)&h[(size_t)r1 * HD + c0 + 8];
    }
    if (r2 < n) {
        x10 = *(const float2*)&h[(size_t)r2 * HD + c0];
        x11 = *(const float2*)&h[(size_t)r2 * HD + c0 + 8];
    }

    uint4 hi, lo;
    split2(x00.x, x00.y, hi.x, lo.x);
    split2(x10.x, x10.y, hi.y, lo.y);
    split2(x01.x, x01.y, hi.z, lo.z);
    split2(x11.x, x11.y, hi.w, lo.w);

    g_Afrag_hi[idx] = hi;
    g_Afrag_lo[idx] = lo;
}

// ---------------------------------------------------------------------------
// prep_B + zero g_cnt (fused)
// ---------------------------------------------------------------------------
__global__ void prep_B_zero(const float* __restrict__ Wq, const float* __restrict__ Wk,
                            const float* __restrict__ Wv, int n) {
    int idx = blockIdx.x * blockDim.x + threadIdx.x;
    if (idx >= 3 * KSTEPS * 16 * 32) {
        int z = idx - 3 * KSTEPS * 16 * 32;
        if (z < n) g_cnt[z] = 0;
        return;
    }
    int lane = idx & 31;
    int j    = (idx >> 5) & 15;
    int s    = (idx >> 9) & 7;
    int m    = idx >> 12;

    const float* W = (m == 0) ? Wq : (m == 1) ? Wk : Wv;
    int nn = j * 8 + (lane >> 2);
    int k0 = s * 16 + (lane & 3) * 2;

    float w00 = W[(size_t)(k0 + 0) * HD + nn];
    float w01 = W[(size_t)(k0 + 1) * HD + nn];
    float w10 = W[(size_t)(k0 + 8) * HD + nn];
    float w11 = W[(size_t)(k0 + 9) * HD + nn];

    uint4 v;
    uint32_t lo0, lo1;
    split2(w00, w01, v.x, lo0);
    split2(w10, w11, v.y, lo1);
    v.z = lo0;
    v.w = lo1;
    g_Bfrag[idx] = v;
}

// ---------------------------------------------------------------------------
// qkv_mma: per-matrix HMMA GEMM, TWO 16-row tiles per warp (each B fragment
// from smem feeds 6 MMAs instead of 3 -> LDS traffic per MMA halved).
// grid (TILES/8, 3), 128 threads. jh-split keeps acc at 2*8*4 = 64 regs.
// Epilogue: m==0 -> g_Q fp32; m==1 -> g_KV comps 0/1; m==2 -> comps 2/3.
// ---------------------------------------------------------------------------
__global__ void __launch_bounds__(128, 4)
qkv_mma(const float* __restrict__ bq, const float* __restrict__ bk,
        const float* __restrict__ bv) {
    __shared__ uint4 sB[4 * 256];      // 16KB: 4 ksteps x 8 j x 32 lanes
    __shared__ float sbias[128];

    const int tid  = threadIdx.x;
    const int wid  = tid >> 5;
    const int lane = tid & 31;
    const int m    = blockIdx.y;
    const int tile0 = blockIdx.x * 8 + wid * 2;   // warp owns tile0, tile0+1

    const float* bias = (m == 0) ? bq : (m == 1) ? bk : bv;
    sbias[tid] = bias[tid];

    const uint4* Ah0 = &g_Afrag_hi[(size_t)tile0 * 256 + lane];
    const uint4* Al0 = &g_Afrag_lo[(size_t)tile0 * 256 + lane];
    const uint4* Ah1 = Ah0 + 256;
    const uint4* Al1 = Al0 + 256;

    const int r1 = tile0 * 16 + (lane >> 2);      // tile0 rows

#pragma unroll
    for (int jh = 0; jh < 2; jh++) {
        float acc[2][8][4];
#pragma unroll
        for (int t = 0; t < 2; t++)
#pragma unroll
            for (int j = 0; j < 8; j++)
#pragma unroll
                for (int r = 0; r < 4; r++) acc[t][j][r] = 0.f;

#pragma unroll
        for (int ph = 0; ph < 2; ph++) {
            __syncthreads();
            // load 1024 uint4 (16KB): sB[s4*256 + jj*32 + ln]
#pragma unroll
            for (int i = 0; i < 8; i++) {
                int idx = tid + i * 128;
                int s4  = idx >> 8;
                int jj  = (idx >> 5) & 7;
                int ln  = idx & 31;
                sB[idx] = __ldg(&g_Bfrag[(size_t)((m * 8 + ph * 4 + s4) * 16 +
                                                  jh * 8 + jj) * 32 + ln]);
            }
            __syncthreads();

#pragma unroll
            for (int s4 = 0; s4 < 4; s4++) {
                const int s = ph * 4 + s4;
                const uint4 ah0 = Ah0[s * 32];
                const uint4 al0 = Al0[s * 32];
                const uint4 ah1 = Ah1[s * 32];
                const uint4 al1 = Al1[s * 32];
#pragma unroll
                for (int jj = 0; jj < 8; jj++) {
                    const uint4 b = sB[s4 * 256 + jj * 32 + lane];
                    MMA16816(acc[0][jj], ah0.x, ah0.y, ah0.z, ah0.w, b.x, b.y);
                    MMA16816(acc[0][jj], al0.x, al0.y, al0.z, al0.w, b.x, b.y);
                    MMA16816(acc[0][jj], ah0.x, ah0.y, ah0.z, ah0.w, b.z, b.w);
                    MMA16816(acc[1][jj], ah1.x, ah1.y, ah1.z, ah1.w, b.x, b.y);
                    MMA16816(acc[1][jj], al1.x, al1.y, al1.z, al1.w, b.x, b.y);
                    MMA16816(acc[1][jj], ah1.x, ah1.y, ah1.z, ah1.w, b.z, b.w);
                }
            }
        }

        // epilogue for this jh half (columns jh*64 .. jh*64+63)
#pragma unroll
        for (int t = 0; t < 2; t++) {
            const int ra = r1 + t * 16;
            const int rb = ra + 8;
#pragma unroll
            for (int jj = 0; jj < 8; jj++) {
                const int c0 = (jh * 8 + jj) * 8 + (lane & 3) * 2;
                float o0 = acc[t][jj][0] + sbias[c0];
                float o1 = acc[t][jj][1] + sbias[c0 + 1];
                float o2 = acc[t][jj][2] + sbias[c0];
                float o3 = acc[t][jj][3] + sbias[c0 + 1];

                if (m == 0) {
                    *(float2*)&g_Q[(size_t)ra * HD + c0] = make_float2(o0, o1);
                    *(float2*)&g_Q[(size_t)rb * HD + c0] = make_float2(o2, o3);
                } else {
                    const int kvlane = c0 >> 2;
                    const int pi     = (c0 >> 1) & 1;
                    const int ci     = (m == 1) ? pi : 2 + pi;
                    __half2 p1 = __floats2half2_rn(o0, o1);
                    __half2 p2 = __floats2half2_rn(o2, o3);
                    ((uint32_t*)&g_KV[(size_t)ra * 32 + kvlane])[ci] = *(uint32_t*)&p1;
                    ((uint32_t*)&g_KV[(size_t)rb * 32 + kvlane])[ci] = *(uint32_t*)&p2;
                }
            }
        }
    }
}

// ---------------------------------------------------------------------------
// Counting sort by dst
// ---------------------------------------------------------------------------
__global__ void hist_kernel(const int* __restrict__ dst, int E) {
    int E4 = E >> 2;
    for (int i = blockIdx.x * blockDim.x + threadIdx.x; i < E4;
         i += gridDim.x * blockDim.x) {
        int4 d = ((const int4*)dst)[i];
        atomicAdd(&g_cnt[d.x], 1);
        atomicAdd(&g_cnt[d.y], 1);
        atomicAdd(&g_cnt[d.z], 1);
        atomicAdd(&g_cnt[d.w], 1);
    }
    int i = E4 * 4 + blockIdx.x * blockDim.x + threadIdx.x;
    if (i < E) atomicAdd(&g_cnt[dst[i]], 1);
}

#define SCAN_T 1024
__global__ void scan_kernel(int n) {
    __shared__ int ssum[SCAN_T];
    const int tid = threadIdx.x;
    const int per = (n + SCAN_T - 1) / SCAN_T;
    const int start = tid * per;
    const int end   = min(start + per, n);

    int s = 0;
    for (int i = start; i < end; i++) s += g_cnt[i];
    ssum[tid] = s;
    __syncthreads();

    for (int off = 1; off < SCAN_T; off <<= 1) {
        int t = (tid >= off) ? ssum[tid - off] : 0;
        __syncthreads();
        ssum[tid] += t;
        __syncthreads();
    }

    int run = ssum[tid] - s;
    for (int i = start; i < end; i++) {
        int c = g_cnt[i];
        g_off[i] = run;
        g_pos[i] = run;
        run += c;
    }
    if (tid == SCAN_T - 1) g_off[n] = run;
}

__global__ void scatter_kernel(const int* __restrict__ src,
                               const int* __restrict__ dst, int E) {
    for (int i = blockIdx.x * blockDim.x + threadIdx.x; i < E;
         i += gridDim.x * blockDim.x) {
        int d = dst[i];
        int p = atomicAdd(&g_pos[d], 1);
        g_esrc[p] = src[i];
    }
}

// ---------------------------------------------------------------------------
// Gather: one warp per node. 8-edge batches staged in SMEM via cp.async
// (no register cost for the batch buffer -> high occupancy). Same-lane
// write/read in smem, so cp.async.wait_group 0 suffices (no barrier).
// Tail edges: clamped address + zeroed score (always-valid data, no NaN).
// ---------------------------------------------------------------------------
__global__ void __launch_bounds__(256, 5)
gather_kernel(float* __restrict__ out, int n) {
    __shared__ __align__(16) uint4 sbuf[8][8][32];   // [warp][edge][lane], 32KB

    const int wslot = threadIdx.x >> 5;
    const int lane  = threadIdx.x & 31;
    int node = (blockIdx.x * blockDim.x + threadIdx.x) >> 5;
    if (node >= n) return;

    const uint32_t sb = smem_u32(&sbuf[wslot][0][lane]);  // +512 per edge slot

    const float4 q4 = *(const float4*)&g_Q[(size_t)node * HD + lane * 4];

    float ax = 0.f, ay = 0.f, az = 0.f, aw = 0.f;
    float zacc = 0.f;

    const int beg  = g_off[node];
    const int endo = g_off[node + 1];

    for (int ebase = beg; ebase < endo; ebase += 8) {
#pragma unroll
        for (int u = 0; u < 8; u++) {
            int e = ebase + u;
            int s = __ldg(&g_esrc[e < endo ? e : endo - 1]);
            const uint4* gp = &g_KV[(size_t)s * 32 + lane];
            asm volatile("cp.async.cg.shared.global [%0], [%1], 16;"
                         :: "r"(sb + u * 512), "l"(gp));
        }
        asm volatile("cp.async.commit_group;" ::: "memory");
        asm volatile("cp.async.wait_group 0;" ::: "memory");

#pragma unroll
        for (int u = 0; u < 8; u++) {
            uint4 kv = sbuf[wslot][u][lane];

            float2 k01 = __half22float2(*reinterpret_cast<__half2*>(&kv.x));
            float2 k23 = __half22float2(*reinterpret_cast<__half2*>(&kv.y));

            float p = k01.x * q4.x + k01.y * q4.y + k23.x * q4.z + k23.y * q4.w;
            p += __shfl_xor_sync(0xffffffffu, p, 1);
            p += __shfl_xor_sync(0xffffffffu, p, 2);

            float sc = __expf(fminf(fmaxf(p * 0.25f, -5.0f), 5.0f));
            sc = (ebase + u < endo) ? sc : 0.f;

            float2 v01 = __half22float2(*reinterpret_cast<__half2*>(&kv.z));
            float2 v23 = __half22float2(*reinterpret_cast<__half2*>(&kv.w));

            ax += v01.x * sc;
            ay += v01.y * sc;
            az += v23.x * sc;
            aw += v23.y * sc;
            zacc += sc;
        }
    }

    float inv = 1.0f / (zacc + 1e-6f);
    float4 o = make_float4(ax * inv, ay * inv, az * inv, aw * inv);
    *(float4*)&out[(size_t)node * HD + lane * 4] = o;
}

// ---------------------------------------------------------------------------
extern "C" void kernel_launch(void* const* d_in, const int* in_sizes, int n_in,
                              void* d_out, int out_size) {
    const float* h  = (const float*)d_in[0];
    const float* Wq = (const float*)d_in[1];
    const float* bq = (const float*)d_in[2];
    const float* Wk = (const float*)d_in[3];
    const float* bk = (const float*)d_in[4];
    const float* Wv = (const float*)d_in[5];
    const float* bv = (const float*)d_in[6];
    const int*  src = (const int*)d_in[7];
    const int*  dst = (const int*)d_in[8];
    float* out = (float*)d_out;

    const int n = in_sizes[0] / HD;
    const int E = in_sizes[7];

    // #1 prep_A, #2 prep_B(+zero cnt), #3 hist, #4 qkv_mma (profiled slot),
    // #5 scan, #6 scatter, #7 gather
    prep_A<<<TILES, 256>>>(h, n);
    prep_B_zero<<<(3 * KSTEPS * 16 * 32 + MAXN + 255) / 256, 256>>>(Wq, Wk, Wv, n);
    hist_kernel<<<1184, 256>>>(dst, E);
    dim3 gg(TILES / 8, 3);
    qkv_mma<<<gg, 128>>>(bq, bk, bv);
    scan_kernel<<<1, SCAN_T>>>(n);
    scatter_kernel<<<2368, 256>>>(src, dst, E);
    gather_kernel<<<(n * 32 + 255) / 256, 256>>>(out, n);
}

// round 11
// speedup vs baseline: 1.0644x; 1.0644x over previous
#include <cuda_runtime.h>
#include <cuda_bf16.h>
#include <cuda_fp16.h>
#include <math.h>
#include <cstdint>

#define HD       128
#define MAXN     50000
#define MAXN_PAD 50048            // 782 * 64
#define MAXE     1600000
#define TILES    (MAXN_PAD / 16)  // 3128 (16-row warp tiles)
#define KSTEPS   8

// ---------------------------------------------------------------------------
// Device scratch (allocation-free per harness rules)
// ---------------------------------------------------------------------------
__device__ float g_Q[MAXN_PAD * HD];
// Interleaved K/V, fp16: g_KV[node*32 + l] = {K2(4l),K2(4l+2),V2(4l),V2(4l+2)}
__device__ uint4 g_KV[MAXN_PAD * 32];

// Fragment-major A (bf16 hi/lo): [tile][kstep][lane] -> uint4 (4 b32 = 8 bf16)
__device__ uint4 g_Afrag_hi[TILES * KSTEPS * 32];
__device__ uint4 g_Afrag_lo[TILES * KSTEPS * 32];
// Fragment-major B: [mat][kstep][ntile][lane] -> uint4 {b0hi,b1hi,b0lo,b1lo}
__device__ uint4 g_Bfrag[3 * KSTEPS * 16 * 32];

// CSR sort scratch
__device__ int g_cnt[MAXN];
__device__ int g_off[MAXN + 1];
__device__ int g_pos[MAXN];
__device__ int g_esrc[MAXE];

// ---------------------------------------------------------------------------
// Helpers
// ---------------------------------------------------------------------------
__device__ __forceinline__ void split2(float x, float y, uint32_t& hi, uint32_t& lo) {
    __nv_bfloat16 hx = __float2bfloat16(x);
    __nv_bfloat16 hy = __float2bfloat16(y);
    __nv_bfloat16 lx = __float2bfloat16(x - __bfloat162float(hx));
    __nv_bfloat16 ly = __float2bfloat16(y - __bfloat162float(hy));
    __nv_bfloat162 H(hx, hy), L(lx, ly);
    hi = *(uint32_t*)&H;
    lo = *(uint32_t*)&L;
}

#define MMA16816(c, a0, a1, a2, a3, b0, b1)                                  \
    asm volatile(                                                            \
        "mma.sync.aligned.m16n8k16.row.col.f32.bf16.bf16.f32 "              \
        "{%0,%1,%2,%3}, {%4,%5,%6,%7}, {%8,%9}, {%0,%1,%2,%3};"             \
        : "+f"((c)[0]), "+f"((c)[1]), "+f"((c)[2]), "+f"((c)[3])             \
        : "r"(a0), "r"(a1), "r"(a2), "r"(a3), "r"(b0), "r"(b1))

// ---------------------------------------------------------------------------
// prep_A: h (fp32) -> bf16 hi/lo fragments. One thread per (tile, kstep, lane).
// ---------------------------------------------------------------------------
__global__ void prep_A(const float* __restrict__ h, int n) {
    int idx = blockIdx.x * blockDim.x + threadIdx.x;
    int lane = idx & 31;
    int s    = (idx >> 5) & 7;
    int t    = idx >> 8;
    if (t >= TILES) return;

    int r1 = t * 16 + (lane >> 2);
    int r2 = r1 + 8;
    int c0 = s * 16 + (lane & 3) * 2;

    float2 x00 = make_float2(0.f, 0.f), x10 = x00, x01 = x00, x11 = x00;
    if (r1 < n) {
        x00 = *(const float2*)&h[(size_t)r1 * HD + c0];
        x01 = *(const float2*)&h[(size_t)r1 * HD + c0 + 8];
    }
    if (r2 < n) {
        x10 = *(const float2*)&h[(size_t)r2 * HD + c0];
        x11 = *(const float2*)&h[(size_t)r2 * HD + c0 + 8];
    }

    uint4 hi, lo;
    split2(x00.x, x00.y, hi.x, lo.x);
    split2(x10.x, x10.y, hi.y, lo.y);
    split2(x01.x, x01.y, hi.z, lo.z);
    split2(x11.x, x11.y, hi.w, lo.w);

    g_Afrag_hi[idx] = hi;
    g_Afrag_lo[idx] = lo;
}

// ---------------------------------------------------------------------------
// prep_B + zero g_cnt (fused)
// ---------------------------------------------------------------------------
__global__ void prep_B_zero(const float* __restrict__ Wq, const float* __restrict__ Wk,
                            const float* __restrict__ Wv, int n) {
    int idx = blockIdx.x * blockDim.x + threadIdx.x;
    if (idx >= 3 * KSTEPS * 16 * 32) {
        int z = idx - 3 * KSTEPS * 16 * 32;
        if (z < n) g_cnt[z] = 0;
        return;
    }
    int lane = idx & 31;
    int j    = (idx >> 5) & 15;
    int s    = (idx >> 9) & 7;
    int m    = idx >> 12;

    const float* W = (m == 0) ? Wq : (m == 1) ? Wk : Wv;
    int nn = j * 8 + (lane >> 2);
    int k0 = s * 16 + (lane & 3) * 2;

    float w00 = W[(size_t)(k0 + 0) * HD + nn];
    float w01 = W[(size_t)(k0 + 1) * HD + nn];
    float w10 = W[(size_t)(k0 + 8) * HD + nn];
    float w11 = W[(size_t)(k0 + 9) * HD + nn];

    uint4 v;
    uint32_t lo0, lo1;
    split2(w00, w01, v.x, lo0);
    split2(w10, w11, v.y, lo1);
    v.z = lo0;
    v.w = lo1;
    g_Bfrag[idx] = v;
}

// ---------------------------------------------------------------------------
// qkv_mma (R10 measured-best): per-matrix HMMA GEMM, TWO 16-row tiles per
// warp (each B fragment from smem feeds 6 MMAs). grid (TILES/8, 3).
// ---------------------------------------------------------------------------
__global__ void __launch_bounds__(128, 4)
qkv_mma(const float* __restrict__ bq, const float* __restrict__ bk,
        const float* __restrict__ bv) {
    __shared__ uint4 sB[4 * 256];      // 16KB: 4 ksteps x 8 j x 32 lanes
    __shared__ float sbias[128];

    const int tid  = threadIdx.x;
    const int wid  = tid >> 5;
    const int lane = tid & 31;
    const int m    = blockIdx.y;
    const int tile0 = blockIdx.x * 8 + wid * 2;   // warp owns tile0, tile0+1

    const float* bias = (m == 0) ? bq : (m == 1) ? bk : bv;
    sbias[tid] = bias[tid];

    const uint4* Ah0 = &g_Afrag_hi[(size_t)tile0 * 256 + lane];
    const uint4* Al0 = &g_Afrag_lo[(size_t)tile0 * 256 + lane];
    const uint4* Ah1 = Ah0 + 256;
    const uint4* Al1 = Al0 + 256;

    const int r1 = tile0 * 16 + (lane >> 2);

#pragma unroll
    for (int jh = 0; jh < 2; jh++) {
        float acc[2][8][4];
#pragma unroll
        for (int t = 0; t < 2; t++)
#pragma unroll
            for (int j = 0; j < 8; j++)
#pragma unroll
                for (int r = 0; r < 4; r++) acc[t][j][r] = 0.f;

#pragma unroll
        for (int ph = 0; ph < 2; ph++) {
            __syncthreads();
#pragma unroll
            for (int i = 0; i < 8; i++) {
                int idx = tid + i * 128;
                int s4  = idx >> 8;
                int jj  = (idx >> 5) & 7;
                int ln  = idx & 31;
                sB[idx] = __ldg(&g_Bfrag[(size_t)((m * 8 + ph * 4 + s4) * 16 +
                                                  jh * 8 + jj) * 32 + ln]);
            }
            __syncthreads();

#pragma unroll
            for (int s4 = 0; s4 < 4; s4++) {
                const int s = ph * 4 + s4;
                const uint4 ah0 = Ah0[s * 32];
                const uint4 al0 = Al0[s * 32];
                const uint4 ah1 = Ah1[s * 32];
                const uint4 al1 = Al1[s * 32];
#pragma unroll
                for (int jj = 0; jj < 8; jj++) {
                    const uint4 b = sB[s4 * 256 + jj * 32 + lane];
                    MMA16816(acc[0][jj], ah0.x, ah0.y, ah0.z, ah0.w, b.x, b.y);
                    MMA16816(acc[0][jj], al0.x, al0.y, al0.z, al0.w, b.x, b.y);
                    MMA16816(acc[0][jj], ah0.x, ah0.y, ah0.z, ah0.w, b.z, b.w);
                    MMA16816(acc[1][jj], ah1.x, ah1.y, ah1.z, ah1.w, b.x, b.y);
                    MMA16816(acc[1][jj], al1.x, al1.y, al1.z, al1.w, b.x, b.y);
                    MMA16816(acc[1][jj], ah1.x, ah1.y, ah1.z, ah1.w, b.z, b.w);
                }
            }
        }

#pragma unroll
        for (int t = 0; t < 2; t++) {
            const int ra = r1 + t * 16;
            const int rb = ra + 8;
#pragma unroll
            for (int jj = 0; jj < 8; jj++) {
                const int c0 = (jh * 8 + jj) * 8 + (lane & 3) * 2;
                float o0 = acc[t][jj][0] + sbias[c0];
                float o1 = acc[t][jj][1] + sbias[c0 + 1];
                float o2 = acc[t][jj][2] + sbias[c0];
                float o3 = acc[t][jj][3] + sbias[c0 + 1];

                if (m == 0) {
                    *(float2*)&g_Q[(size_t)ra * HD + c0] = make_float2(o0, o1);
                    *(float2*)&g_Q[(size_t)rb * HD + c0] = make_float2(o2, o3);
                } else {
                    const int kvlane = c0 >> 2;
                    const int pi     = (c0 >> 1) & 1;
                    const int ci     = (m == 1) ? pi : 2 + pi;
                    __half2 p1 = __floats2half2_rn(o0, o1);
                    __half2 p2 = __floats2half2_rn(o2, o3);
                    ((uint32_t*)&g_KV[(size_t)ra * 32 + kvlane])[ci] = *(uint32_t*)&p1;
                    ((uint32_t*)&g_KV[(size_t)rb * 32 + kvlane])[ci] = *(uint32_t*)&p2;
                }
            }
        }
    }
}

// ---------------------------------------------------------------------------
// Counting sort by dst
// ---------------------------------------------------------------------------
__global__ void hist_kernel(const int* __restrict__ dst, int E) {
    int E4 = E >> 2;
    for (int i = blockIdx.x * blockDim.x + threadIdx.x; i < E4;
         i += gridDim.x * blockDim.x) {
        int4 d = ((const int4*)dst)[i];
        atomicAdd(&g_cnt[d.x], 1);
        atomicAdd(&g_cnt[d.y], 1);
        atomicAdd(&g_cnt[d.z], 1);
        atomicAdd(&g_cnt[d.w], 1);
    }
    int i = E4 * 4 + blockIdx.x * blockDim.x + threadIdx.x;
    if (i < E) atomicAdd(&g_cnt[dst[i]], 1);
}

#define SCAN_T 1024
__global__ void scan_kernel(int n) {
    __shared__ int ssum[SCAN_T];
    const int tid = threadIdx.x;
    const int per = (n + SCAN_T - 1) / SCAN_T;
    const int start = tid * per;
    const int end   = min(start + per, n);

    int s = 0;
    for (int i = start; i < end; i++) s += g_cnt[i];
    ssum[tid] = s;
    __syncthreads();

    for (int off = 1; off < SCAN_T; off <<= 1) {
        int t = (tid >= off) ? ssum[tid - off] : 0;
        __syncthreads();
        ssum[tid] += t;
        __syncthreads();
    }

    int run = ssum[tid] - s;
    for (int i = start; i < end; i++) {
        int c = g_cnt[i];
        g_off[i] = run;
        g_pos[i] = run;
        run += c;
    }
    if (tid == SCAN_T - 1) g_off[n] = run;
}

__global__ void scatter_kernel(const int* __restrict__ src,
                               const int* __restrict__ dst, int E) {
    for (int i = blockIdx.x * blockDim.x + threadIdx.x; i < E;
         i += gridDim.x * blockDim.x) {
        int d = dst[i];
        int p = atomicAdd(&g_pos[d], 1);
        g_esrc[p] = src[i];
    }
}

// ---------------------------------------------------------------------------
// Gather (R8 exact, known-good): one warp per node; 8-edge register batches;
// ONE LDG.128 per lane per edge from interleaved g_KV.
// ---------------------------------------------------------------------------
__global__ void gather_kernel(float* __restrict__ out, int n) {
    int node = (blockIdx.x * blockDim.x + threadIdx.x) >> 5;
    if (node >= n) return;
    const int lane = threadIdx.x & 31;

    const float4 q4 = *(const float4*)&g_Q[(size_t)node * HD + lane * 4];

    float ax = 0.f, ay = 0.f, az = 0.f, aw = 0.f;
    float zacc = 0.f;

    const int beg  = g_off[node];
    const int endo = g_off[node + 1];

    for (int ebase = beg; ebase < endo; ebase += 32) {
        int eidx = ebase + lane;
        int my_s = (eidx < endo) ? g_esrc[eidx] : 0;
        int cnt = endo - ebase;
        if (cnt > 32) cnt = 32;

        int j = 0;
        for (; j + 8 <= cnt; j += 8) {
            uint4 kv[8];
#pragma unroll
            for (int u = 0; u < 8; u++) {
                int s = __shfl_sync(0xffffffffu, my_s, j + u);
                kv[u] = g_KV[(size_t)s * 32 + lane];
            }
#pragma unroll
            for (int u = 0; u < 8; u++) {
                float2 k01 = __half22float2(*reinterpret_cast<__half2*>(&kv[u].x));
                float2 k23 = __half22float2(*reinterpret_cast<__half2*>(&kv[u].y));

                float p = k01.x * q4.x + k01.y * q4.y + k23.x * q4.z + k23.y * q4.w;
                p += __shfl_xor_sync(0xffffffffu, p, 1);
                p += __shfl_xor_sync(0xffffffffu, p, 2);

                float sc = __expf(fminf(fmaxf(p * 0.25f, -5.0f), 5.0f));

                float2 v01 = __half22float2(*reinterpret_cast<__half2*>(&kv[u].z));
                float2 v23 = __half22float2(*reinterpret_cast<__half2*>(&kv[u].w));

                ax += v01.x * sc;
                ay += v01.y * sc;
                az += v23.x * sc;
                aw += v23.y * sc;
                zacc += sc;
            }
        }
        for (; j < cnt; j++) {
            int s = __shfl_sync(0xffffffffu, my_s, j);
            uint4 kv = g_KV[(size_t)s * 32 + lane];

            float2 k01 = __half22float2(*reinterpret_cast<__half2*>(&kv.x));
            float2 k23 = __half22float2(*reinterpret_cast<__half2*>(&kv.y));

            float p = k01.x * q4.x + k01.y * q4.y + k23.x * q4.z + k23.y * q4.w;
            p += __shfl_xor_sync(0xffffffffu, p, 1);
            p += __shfl_xor_sync(0xffffffffu, p, 2);

            float sc = __expf(fminf(fmaxf(p * 0.25f, -5.0f), 5.0f));

            float2 v01 = __half22float2(*reinterpret_cast<__half2*>(&kv.z));
            float2 v23 = __half22float2(*reinterpret_cast<__half2*>(&kv.w));

            ax += v01.x * sc;
            ay += v01.y * sc;
            az += v23.x * sc;
            aw += v23.y * sc;
            zacc += sc;
        }
    }

    float inv = 1.0f / (zacc + 1e-6f);
    float4 o = make_float4(ax * inv, ay * inv, az * inv, aw * inv);
    *(float4*)&out[(size_t)node * HD + lane * 4] = o;
}

// ---------------------------------------------------------------------------
extern "C" void kernel_launch(void* const* d_in, const int* in_sizes, int n_in,
                              void* d_out, int out_size) {
    const float* h  = (const float*)d_in[0];
    const float* Wq = (const float*)d_in[1];
    const float* bq = (const float*)d_in[2];
    const float* Wk = (const float*)d_in[3];
    const float* bk = (const float*)d_in[4];
    const float* Wv = (const float*)d_in[5];
    const float* bv = (const float*)d_in[6];
    const int*  src = (const int*)d_in[7];
    const int*  dst = (const int*)d_in[8];
    float* out = (float*)d_out;

    const int n = in_sizes[0] / HD;
    const int E = in_sizes[7];

    // #1 prep_A, #2 prep_B(+zero cnt), #3 hist, #4 qkv_mma (profiled slot),
    // #5 scan, #6 scatter, #7 gather
    prep_A<<<TILES, 256>>>(h, n);
    prep_B_zero<<<(3 * KSTEPS * 16 * 32 + MAXN + 255) / 256, 256>>>(Wq, Wk, Wv, n);
    hist_kernel<<<1184, 256>>>(dst, E);
    dim3 gg(TILES / 8, 3);
    qkv_mma<<<gg, 128>>>(bq, bk, bv);
    scan_kernel<<<1, SCAN_T>>>(n);
    scatter_kernel<<<2368, 256>>>(src, dst, E);
    gather_kernel<<<(n * 32 + 255) / 256, 256>>>(out, n);
}

// round 12
// speedup vs baseline: 1.0873x; 1.0216x over previous
#include <cuda_runtime.h>
#include <cuda_bf16.h>
#include <cuda_fp16.h>
#include <math.h>
#include <cstdint>

#define HD       128
#define MAXN     50000
#define MAXN_PAD 50176            // 3136 * 16 (16 tiles per 256-thr mma block)
#define MAXE     1600000
#define TILES    (MAXN_PAD / 16)  // 3136
#define KSTEPS   8

#define PREPB_THREADS (3 * KSTEPS * 16 * 32)   // 12288
#define PREPB_BLKS    (PREPB_THREADS / 256)    // 48
#define HIST_BLKS     1184
#define MMA_BLKS      (TILES / 16)             // 196
#define SCAT_BLKS     790

// ---------------------------------------------------------------------------
// Device scratch (allocation-free; zero-initialized at module load)
// ---------------------------------------------------------------------------
__device__ float g_Q[MAXN_PAD * HD];
// Interleaved K/V, fp16: g_KV[node*32 + l] = {K2(4l),K2(4l+2),V2(4l),V2(4l+2)}
__device__ uint4 g_KV[MAXN_PAD * 32];

__device__ uint4 g_Afrag_hi[TILES * KSTEPS * 32];
__device__ uint4 g_Afrag_lo[TILES * KSTEPS * 32];
__device__ uint4 g_Bfrag[3 * KSTEPS * 16 * 32];

// CSR sort scratch. g_cnt starts zero (module init) and is re-zeroed by the
// gather epilogue each call, so no explicit zero kernel is needed.
__device__ int g_cnt[MAXN];
__device__ int g_off[MAXN + 1];
__device__ int g_pos[MAXN];
__device__ int g_esrc[MAXE];

// ---------------------------------------------------------------------------
// Helpers
// ---------------------------------------------------------------------------
__device__ __forceinline__ void split2(float x, float y, uint32_t& hi, uint32_t& lo) {
    __nv_bfloat16 hx = __float2bfloat16(x);
    __nv_bfloat16 hy = __float2bfloat16(y);
    __nv_bfloat16 lx = __float2bfloat16(x - __bfloat162float(hx));
    __nv_bfloat16 ly = __float2bfloat16(y - __bfloat162float(hy));
    __nv_bfloat162 H(hx, hy), L(lx, ly);
    hi = *(uint32_t*)&H;
    lo = *(uint32_t*)&L;
}

#define MMA16816(c, a0, a1, a2, a3, b0, b1)                                  \
    asm volatile(                                                            \
        "mma.sync.aligned.m16n8k16.row.col.f32.bf16.bf16.f32 "              \
        "{%0,%1,%2,%3}, {%4,%5,%6,%7}, {%8,%9}, {%0,%1,%2,%3};"             \
        : "+f"((c)[0]), "+f"((c)[1]), "+f"((c)[2]), "+f"((c)[3])             \
        : "r"(a0), "r"(a1), "r"(a2), "r"(a3), "r"(b0), "r"(b1))

// ---------------------------------------------------------------------------
// K1: prep_A (blocks [0,TILES)) + prep_B (next 48) + hist (rest). All
// mutually independent. g_cnt is pre-zeroed (module init / gather epilogue).
// ---------------------------------------------------------------------------
__global__ void prep_hist_kernel(const float* __restrict__ h,
                                 const float* __restrict__ Wq,
                                 const float* __restrict__ Wk,
                                 const float* __restrict__ Wv,
                                 const int* __restrict__ dst,
                                 int n, int E) {
    const int b = blockIdx.x;
    const int tid = threadIdx.x;

    if (b < TILES) {
        // ---- prep_A: tile t = b; 256 threads = 8 ksteps x 32 lanes
        int idx = b * 256 + tid;
        int lane = idx & 31;
        int s    = (idx >> 5) & 7;
        int t    = b;

        int r1 = t * 16 + (lane >> 2);
        int r2 = r1 + 8;
        int c0 = s * 16 + (lane & 3) * 2;

        float2 x00 = make_float2(0.f, 0.f), x10 = x00, x01 = x00, x11 = x00;
        if (r1 < n) {
            x00 = *(const float2*)&h[(size_t)r1 * HD + c0];
            x01 = *(const float2*)&h[(size_t)r1 * HD + c0 + 8];
        }
        if (r2 < n) {
            x10 = *(const float2*)&h[(size_t)r2 * HD + c0];
            x11 = *(const float2*)&h[(size_t)r2 * HD + c0 + 8];
        }

        uint4 hi, lo;
        split2(x00.x, x00.y, hi.x, lo.x);
        split2(x10.x, x10.y, hi.y, lo.y);
        split2(x01.x, x01.y, hi.z, lo.z);
        split2(x11.x, x11.y, hi.w, lo.w);

        g_Afrag_hi[idx] = hi;
        g_Afrag_lo[idx] = lo;
    } else if (b < TILES + PREPB_BLKS) {
        // ---- prep_B
        int idx = (b - TILES) * 256 + tid;
        int lane = idx & 31;
        int j    = (idx >> 5) & 15;
        int s    = (idx >> 9) & 7;
        int m    = idx >> 12;

        const float* W = (m == 0) ? Wq : (m == 1) ? Wk : Wv;
        int nn = j * 8 + (lane >> 2);
        int k0 = s * 16 + (lane & 3) * 2;

        float w00 = W[(size_t)(k0 + 0) * HD + nn];
        float w01 = W[(size_t)(k0 + 1) * HD + nn];
        float w10 = W[(size_t)(k0 + 8) * HD + nn];
        float w11 = W[(size_t)(k0 + 9) * HD + nn];

        uint4 v;
        uint32_t lo0, lo1;
        split2(w00, w01, v.x, lo0);
        split2(w10, w11, v.y, lo1);
        v.z = lo0;
        v.w = lo1;
        g_Bfrag[idx] = v;
    } else {
        // ---- hist (vectorized int4 + tail)
        int hb = b - TILES - PREPB_BLKS;     // 0..HIST_BLKS-1
        int E4 = E >> 2;
        for (int i = hb * 256 + tid; i < E4; i += HIST_BLKS * 256) {
            int4 d = ((const int4*)dst)[i];
            atomicAdd(&g_cnt[d.x], 1);
            atomicAdd(&g_cnt[d.y], 1);
            atomicAdd(&g_cnt[d.z], 1);
            atomicAdd(&g_cnt[d.w], 1);
        }
        int i = E4 * 4 + hb * 256 + tid;
        if (i < E) atomicAdd(&g_cnt[dst[i]], 1);
    }
}

// ---------------------------------------------------------------------------
// K2: scan (exclusive prefix sum of g_cnt -> g_off, g_pos)
// ---------------------------------------------------------------------------
#define SCAN_T 1024
__global__ void scan_kernel(int n) {
    __shared__ int ssum[SCAN_T];
    const int tid = threadIdx.x;
    const int per = (n + SCAN_T - 1) / SCAN_T;
    const int start = tid * per;
    const int end   = min(start + per, n);

    int s = 0;
    for (int i = start; i < end; i++) s += g_cnt[i];
    ssum[tid] = s;
    __syncthreads();

    for (int off = 1; off < SCAN_T; off <<= 1) {
        int t = (tid >= off) ? ssum[tid - off] : 0;
        __syncthreads();
        ssum[tid] += t;
        __syncthreads();
    }

    int run = ssum[tid] - s;
    for (int i = start; i < end; i++) {
        int c = g_cnt[i];
        g_off[i] = run;
        g_pos[i] = run;
        run += c;
    }
    if (tid == SCAN_T - 1) g_off[n] = run;
}

// ---------------------------------------------------------------------------
// K3: qkv_mma (blocks [0,MMA_BLKS), 8 warps, 2 tiles/warp) + scatter
// (blocks [MMA_BLKS, MMA_BLKS+SCAT_BLKS), replicated over gridDim.y=3 slices).
// mma is tensor/smem-bound, scatter is L2/atomic-bound -> they overlap.
// ---------------------------------------------------------------------------
__global__ void __launch_bounds__(256, 2)
mma_scatter_kernel(const float* __restrict__ bq, const float* __restrict__ bk,
                   const float* __restrict__ bv,
                   const int* __restrict__ src, const int* __restrict__ dst,
                   int E) {
    __shared__ uint4 sB[4 * 256];      // 16KB
    __shared__ float sbias[128];

    const int tid = threadIdx.x;

    if (blockIdx.x >= MMA_BLKS) {
        // ---- scatter slice (y picks a third of the chunks)
        const int cb = (blockIdx.x - MMA_BLKS) + blockIdx.y * SCAT_BLKS;
        for (int i = cb * 256 + tid; i < E; i += 3 * SCAT_BLKS * 256) {
            int d = dst[i];
            int p = atomicAdd(&g_pos[d], 1);
            g_esrc[p] = src[i];
        }
        return;
    }

    // ---- mma: 8 warps, each owns 2 tiles
    const int wid  = tid >> 5;
    const int lane = tid & 31;
    const int m    = blockIdx.y;
    const int tile0 = blockIdx.x * 16 + wid * 2;

    const float* bias = (m == 0) ? bq : (m == 1) ? bk : bv;
    if (tid < 128) sbias[tid] = bias[tid];

    const uint4* Ah0 = &g_Afrag_hi[(size_t)tile0 * 256 + lane];
    const uint4* Al0 = &g_Afrag_lo[(size_t)tile0 * 256 + lane];
    const uint4* Ah1 = Ah0 + 256;
    const uint4* Al1 = Al0 + 256;

    const int r1 = tile0 * 16 + (lane >> 2);

#pragma unroll
    for (int jh = 0; jh < 2; jh++) {
        float acc[2][8][4];
#pragma unroll
        for (int t = 0; t < 2; t++)
#pragma unroll
            for (int j = 0; j < 8; j++)
#pragma unroll
                for (int r = 0; r < 4; r++) acc[t][j][r] = 0.f;

#pragma unroll
        for (int ph = 0; ph < 2; ph++) {
            __syncthreads();
#pragma unroll
            for (int i = 0; i < 4; i++) {
                int idx = tid + i * 256;
                int s4  = idx >> 8;
                int jj  = (idx >> 5) & 7;
                int ln  = idx & 31;
                sB[idx] = __ldg(&g_Bfrag[(size_t)((m * 8 + ph * 4 + s4) * 16 +
                                                  jh * 8 + jj) * 32 + ln]);
            }
            __syncthreads();

#pragma unroll
            for (int s4 = 0; s4 < 4; s4++) {
                const int s = ph * 4 + s4;
                const uint4 ah0 = Ah0[s * 32];
                const uint4 al0 = Al0[s * 32];
                const uint4 ah1 = Ah1[s * 32];
                const uint4 al1 = Al1[s * 32];
#pragma unroll
                for (int jj = 0; jj < 8; jj++) {
                    const uint4 b = sB[s4 * 256 + jj * 32 + lane];
                    MMA16816(acc[0][jj], ah0.x, ah0.y, ah0.z, ah0.w, b.x, b.y);
                    MMA16816(acc[0][jj], al0.x, al0.y, al0.z, al0.w, b.x, b.y);
                    MMA16816(acc[0][jj], ah0.x, ah0.y, ah0.z, ah0.w, b.z, b.w);
                    MMA16816(acc[1][jj], ah1.x, ah1.y, ah1.z, ah1.w, b.x, b.y);
                    MMA16816(acc[1][jj], al1.x, al1.y, al1.z, al1.w, b.x, b.y);
                    MMA16816(acc[1][jj], ah1.x, ah1.y, ah1.z, ah1.w, b.z, b.w);
                }
            }
        }

#pragma unroll
        for (int t = 0; t < 2; t++) {
            const int ra = r1 + t * 16;
            const int rb = ra + 8;
#pragma unroll
            for (int jj = 0; jj < 8; jj++) {
                const int c0 = (jh * 8 + jj) * 8 + (lane & 3) * 2;
                float o0 = acc[t][jj][0] + sbias[c0];
                float o1 = acc[t][jj][1] + sbias[c0 + 1];
                float o2 = acc[t][jj][2] + sbias[c0];
                float o3 = acc[t][jj][3] + sbias[c0 + 1];

                if (m == 0) {
                    *(float2*)&g_Q[(size_t)ra * HD + c0] = make_float2(o0, o1);
                    *(float2*)&g_Q[(size_t)rb * HD + c0] = make_float2(o2, o3);
                } else {
                    const int kvlane = c0 >> 2;
                    const int pi     = (c0 >> 1) & 1;
                    const int ci     = (m == 1) ? pi : 2 + pi;
                    __half2 p1 = __floats2half2_rn(o0, o1);
                    __half2 p2 = __floats2half2_rn(o2, o3);
                    ((uint32_t*)&g_KV[(size_t)ra * 32 + kvlane])[ci] = *(uint32_t*)&p1;
                    ((uint32_t*)&g_KV[(size_t)rb * 32 + kvlane])[ci] = *(uint32_t*)&p2;
                }
            }
        }
    }
}

// ---------------------------------------------------------------------------
// K4: gather (R8 exact) + g_cnt restore-to-zero for the next graph replay.
// One warp per node; 8-edge register batches; ONE LDG.128 per lane per edge.
// ---------------------------------------------------------------------------
__global__ void gather_kernel(float* __restrict__ out, int n) {
    int node = (blockIdx.x * blockDim.x + threadIdx.x) >> 5;
    if (node >= n) return;
    const int lane = threadIdx.x & 31;

    if (lane == 0) g_cnt[node] = 0;   // restore invariant for next call

    const float4 q4 = *(const float4*)&g_Q[(size_t)node * HD + lane * 4];

    float ax = 0.f, ay = 0.f, az = 0.f, aw = 0.f;
    float zacc = 0.f;

    const int beg  = g_off[node];
    const int endo = g_off[node + 1];

    for (int ebase = beg; ebase < endo; ebase += 32) {
        int eidx = ebase + lane;
        int my_s = (eidx < endo) ? g_esrc[eidx] : 0;
        int cnt = endo - ebase;
        if (cnt > 32) cnt = 32;

        int j = 0;
        for (; j + 8 <= cnt; j += 8) {
            uint4 kv[8];
#pragma unroll
            for (int u = 0; u < 8; u++) {
                int s = __shfl_sync(0xffffffffu, my_s, j + u);
                kv[u] = g_KV[(size_t)s * 32 + lane];
            }
#pragma unroll
            for (int u = 0; u < 8; u++) {
                float2 k01 = __half22float2(*reinterpret_cast<__half2*>(&kv[u].x));
                float2 k23 = __half22float2(*reinterpret_cast<__half2*>(&kv[u].y));

                float p = k01.x * q4.x + k01.y * q4.y + k23.x * q4.z + k23.y * q4.w;
                p += __shfl_xor_sync(0xffffffffu, p, 1);
                p += __shfl_xor_sync(0xffffffffu, p, 2);

                float sc = __expf(fminf(fmaxf(p * 0.25f, -5.0f), 5.0f));

                float2 v01 = __half22float2(*reinterpret_cast<__half2*>(&kv[u].z));
                float2 v23 = __half22float2(*reinterpret_cast<__half2*>(&kv[u].w));

                ax += v01.x * sc;
                ay += v01.y * sc;
                az += v23.x * sc;
                aw += v23.y * sc;
                zacc += sc;
            }
        }
        for (; j < cnt; j++) {
            int s = __shfl_sync(0xffffffffu, my_s, j);
            uint4 kv = g_KV[(size_t)s * 32 + lane];

            float2 k01 = __half22float2(*reinterpret_cast<__half2*>(&kv.x));
            float2 k23 = __half22float2(*reinterpret_cast<__half2*>(&kv.y));

            float p = k01.x * q4.x + k01.y * q4.y + k23.x * q4.z + k23.y * q4.w;
            p += __shfl_xor_sync(0xffffffffu, p, 1);
            p += __shfl_xor_sync(0xffffffffu, p, 2);

            float sc = __expf(fminf(fmaxf(p * 0.25f, -5.0f), 5.0f));

            float2 v01 = __half22float2(*reinterpret_cast<__half2*>(&kv.z));
            float2 v23 = __half22float2(*reinterpret_cast<__half2*>(&kv.w));

            ax += v01.x * sc;
            ay += v01.y * sc;
            az += v23.x * sc;
            aw += v23.y * sc;
            zacc += sc;
        }
    }

    float inv = 1.0f / (zacc + 1e-6f);
    float4 o = make_float4(ax * inv, ay * inv, az * inv, aw * inv);
    *(float4*)&out[(size_t)node * HD + lane * 4] = o;
}

// ---------------------------------------------------------------------------
extern "C" void kernel_launch(void* const* d_in, const int* in_sizes, int n_in,
                              void* d_out, int out_size) {
    const float* h  = (const float*)d_in[0];
    const float* Wq = (const float*)d_in[1];
    const float* bq = (const float*)d_in[2];
    const float* Wk = (const float*)d_in[3];
    const float* bk = (const float*)d_in[4];
    const float* Wv = (const float*)d_in[5];
    const float* bv = (const float*)d_in[6];
    const int*  src = (const int*)d_in[7];
    const int*  dst = (const int*)d_in[8];
    float* out = (float*)d_out;

    const int n = in_sizes[0] / HD;
    const int E = in_sizes[7];

    // 4 launches: #1 prep+hist, #2 scan, #3 mma+scatter, #4 gather (profiled)
    prep_hist_kernel<<<TILES + PREPB_BLKS + HIST_BLKS, 256>>>(h, Wq, Wk, Wv, dst, n, E);
    scan_kernel<<<1, SCAN_T>>>(n);
    dim3 g3(MMA_BLKS + SCAT_BLKS, 3);
    mma_scatter_kernel<<<g3, 256>>>(bq, bk, bv, src, dst, E);
    gather_kernel<<<(n * 32 + 255) / 256, 256>>>(out, n);
}